// round 2
// baseline (speedup 1.0000x reference)
#include <cuda_runtime.h>
#include <cstring>
#include <cstddef>

#define NB 4
#define NS 4096
#define ND 2048
#define NE 64
#define NM (NB*NS)          // 16384 tokens
#define TILE_M 64
#define KC 64
#define XSTR 68             // padded row stride for x tile / logits tile
#define NCHUNK (ND/KC)      // 32

// broadcast one float into both lanes of an f32x2 register pair
__device__ __forceinline__ unsigned long long bcast2(float v) {
    unsigned long long r;
    asm("mov.b64 %0, {%1, %1};" : "=l"(r) : "r"(__float_as_uint(v)));
    return r;
}
// packed fp32x2 FMA: d = a*b + d (lanewise)
__device__ __forceinline__ void ffma2(unsigned long long &d,
                                      unsigned long long a,
                                      unsigned long long b) {
    asm("fma.rn.f32x2 %0, %1, %2, %0;" : "+l"(d) : "l"(a), "l"(b));
}

__global__ __launch_bounds__(256)
void router_kernel(const float* __restrict__ x,
                   const float* __restrict__ Wm,
                   const float* __restrict__ bias,
                   const float* __restrict__ noise,
                   float* __restrict__ out)
{
    // smem: x tile [TILE_M][XSTR] + W tile [KC][NE]; x region reused for logits
    __shared__ __align__(16) float smem[TILE_M*XSTR + KC*NE];
    float* xs = smem;
    float* ws = smem + TILE_M*XSTR;

    const int tid = threadIdx.x;
    const int m0  = blockIdx.x * TILE_M;

    const int tg = tid >> 4;        // 0..15 : token group (4 tokens each)
    const int eg = tid & 15;        // 0..15 : expert group (4 experts each)

    const int lrow = tid >> 4;      // loader row 0..15
    const int lc4  = (tid & 15) * 4;

    // acc[i][p]: token 4*tg+i, expert pair (4*eg+2p, 4*eg+2p+1) packed f32x2
    unsigned long long acc[4][2];
    #pragma unroll
    for (int i = 0; i < 4; i++) { acc[i][0] = 0ull; acc[i][1] = 0ull; }

    for (int ch = 0; ch < NCHUNK; ch++) {
        const int k0 = ch * KC;
        // load x tile: 64 tokens x 64 k (coalesced float4)
        #pragma unroll
        for (int i = 0; i < 4; i++) {
            int r = lrow + 16*i;
            float4 v = *(const float4*)&x[(size_t)(m0 + r)*ND + k0 + lc4];
            *(float4*)&xs[r*XSTR + lc4] = v;
        }
        // load W tile: 64 k x 64 experts (coalesced float4, layout kept)
        #pragma unroll
        for (int i = 0; i < 4; i++) {
            int r = lrow + 16*i;
            float4 v = *(const float4*)&Wm[(size_t)(k0 + r)*NE + lc4];
            *(float4*)&ws[r*NE + lc4] = v;
        }
        __syncthreads();

        #pragma unroll 4
        for (int k = 0; k < KC; k++) {
            // W pair values come pre-packed as two f32x2 from one LDS.128
            ulonglong2 w2 = *(const ulonglong2*)&ws[k*NE + 4*eg];
            #pragma unroll
            for (int i = 0; i < 4; i++) {
                unsigned long long xb = bcast2(xs[(4*tg + i)*XSTR + k]);
                ffma2(acc[i][0], xb, w2.x);
                ffma2(acc[i][1], xb, w2.y);
            }
        }
        __syncthreads();
    }

    // ---- epilogue: dump logits to smem (reuse x region) ----
    float* lg = smem;   // [TILE_M][XSTR]
    #pragma unroll
    for (int i = 0; i < 4; i++) {
        #pragma unroll
        for (int p = 0; p < 2; p++) {
            float2 v;
            memcpy(&v, &acc[i][p], 8);
            *(float2*)&lg[(4*tg + i)*XSTR + 4*eg + 2*p] = v;
        }
    }
    __syncthreads();

    if (tid < TILE_M) {
        const int token = m0 + tid;
        float* row = &lg[tid * XSTR];

        // pass 1: add bias + 0.1*noise, track max
        float mx = -3.0e38f;
        #pragma unroll
        for (int j = 0; j < NE/4; j++) {
            float4 v  = *(float4*)&row[4*j];
            float4 nz = *(const float4*)&noise[(size_t)token*NE + 4*j];
            float4 bb = *(const float4*)&bias[4*j];
            v.x += bb.x + 0.1f*nz.x;
            v.y += bb.y + 0.1f*nz.y;
            v.z += bb.z + 0.1f*nz.z;
            v.w += bb.w + 0.1f*nz.w;
            mx = fmaxf(mx, fmaxf(fmaxf(v.x, v.y), fmaxf(v.z, v.w)));
            *(float4*)&row[4*j] = v;
        }

        // pass 2: exp(v - max), sum
        float sum = 0.0f;
        #pragma unroll
        for (int j = 0; j < NE/4; j++) {
            float4 v = *(float4*)&row[4*j];
            v.x = expf(v.x - mx);
            v.y = expf(v.y - mx);
            v.z = expf(v.z - mx);
            v.w = expf(v.w - mx);
            sum += (v.x + v.y) + (v.z + v.w);
            *(float4*)&row[4*j] = v;
        }
        const float inv = 1.0f / sum;

        // pass 3: normalize, write scores, scan top-2 (ties -> lowest index)
        float m1 = -1.0f, m2 = -1.0f;
        int i1 = 0, i2 = 0;
        float* out_sc = out + (size_t)NM*4;
        #pragma unroll
        for (int j = 0; j < NE/4; j++) {
            float4 v = *(float4*)&row[4*j];
            v.x *= inv; v.y *= inv; v.z *= inv; v.w *= inv;
            *(float4*)&out_sc[(size_t)token*NE + 4*j] = v;
            float vs[4] = {v.x, v.y, v.z, v.w};
            #pragma unroll
            for (int l = 0; l < 4; l++) {
                int idx = 4*j + l;
                float val = vs[l];
                if (val > m1)      { m2 = m1; i2 = i1; m1 = val; i1 = idx; }
                else if (val > m2) { m2 = val; i2 = idx; }
            }
        }
        // topk_scores | topk_indices (as float) | scores
        out[(size_t)token*2 + 0] = m1;
        out[(size_t)token*2 + 1] = m2;
        out[(size_t)NM*2 + (size_t)token*2 + 0] = (float)i1;
        out[(size_t)NM*2 + (size_t)token*2 + 1] = (float)i2;
    }
}

extern "C" void kernel_launch(void* const* d_in, const int* in_sizes, int n_in,
                              void* d_out, int out_size) {
    const float* x     = (const float*)d_in[0];
    const float* W     = (const float*)d_in[1];
    const float* b     = (const float*)d_in[2];
    const float* noise = (const float*)d_in[3];
    router_kernel<<<NM / TILE_M, 256>>>(x, W, b, noise, (float*)d_out);
}

// round 6
// speedup vs baseline: 2.1123x; 2.1123x over previous
#include <cuda_runtime.h>
#include <cuda_fp16.h>
#include <cstdint>
#include <cstddef>
#include <cstring>

#define NM 16384
#define ND 2048
#define NE 64
#define TM 128
#define KC 64
#define NCH (ND/KC)   // 32

#define SW128(o) ((o) ^ (((o) >> 3) & 0x70))

__device__ __align__(16) __half g_Whi[NE * ND];
__device__ __align__(16) __half g_Wlo[NE * ND];

// ---------- helpers ----------
__device__ __forceinline__ uint32_t smem_u32(const void* p) {
    uint32_t a;
    asm("{ .reg .u64 t; cvta.to.shared.u64 t, %1; cvt.u32.u64 %0, t; }" : "=r"(a) : "l"(p));
    return a;
}
__device__ __forceinline__ void ldm4(uint32_t* r, uint32_t addr) {
    asm volatile("ldmatrix.sync.aligned.m8n8.x4.shared.b16 {%0,%1,%2,%3}, [%4];"
                 : "=r"(r[0]), "=r"(r[1]), "=r"(r[2]), "=r"(r[3]) : "r"(addr));
}
__device__ __forceinline__ void mma16816(float* d, const uint32_t* a, uint32_t b0, uint32_t b1) {
    asm volatile(
        "mma.sync.aligned.m16n8k16.row.col.f32.f16.f16.f32 "
        "{%0,%1,%2,%3}, {%4,%5,%6,%7}, {%8,%9}, {%0,%1,%2,%3};"
        : "+f"(d[0]), "+f"(d[1]), "+f"(d[2]), "+f"(d[3])
        : "r"(a[0]), "r"(a[1]), "r"(a[2]), "r"(a[3]), "r"(b0), "r"(b1));
}
__device__ __forceinline__ void sts64(uint32_t addr, uint32_t a, uint32_t b) {
    asm volatile("st.shared.v2.b32 [%0], {%1,%2};" :: "r"(addr), "r"(a), "r"(b));
}
__device__ __forceinline__ void sts128(uint32_t addr, uint4 v) {
    asm volatile("st.shared.v4.b32 [%0], {%1,%2,%3,%4};"
                 :: "r"(addr), "r"(v.x), "r"(v.y), "r"(v.z), "r"(v.w));
}

// ---------- W prep: fp32 [K,E] -> fp16 hi/lo, transposed to [E,K] ----------
__global__ void prep_W(const float* __restrict__ W) {
    int idx = blockIdx.x * 256 + threadIdx.x;
    int e = idx >> 11, k = idx & (ND - 1);
    float w = W[k * NE + e];
    __half h = __float2half_rn(w);
    g_Whi[idx] = h;
    g_Wlo[idx] = __float2half_rn(w - __half2float(h));
}

// ---------- main kernel ----------
__global__ __launch_bounds__(256)
void router_mma(const float* __restrict__ x, const float* __restrict__ bias,
                const float* __restrict__ noise, float* __restrict__ out)
{
    __shared__ __align__(128) char smem[49152];
    const uint32_t sb = smem_u32(smem);
    const uint32_t A_HI = sb, A_LO = sb + 16384, B_HI = sb + 32768, B_LO = sb + 40960;

    const int tid = threadIdx.x, wid = tid >> 5, lane = tid & 31;
    const int m0 = blockIdx.x * TM;
    const int wr = wid * 16;

    // ldmatrix per-lane base offsets (within A/B tiles, pre-swizzle)
    const int lr = lane & 7, q = lane >> 3;
    const uint32_t a_base = (uint32_t)((wr + (q & 1) * 8 + lr) * 128 + ((q >> 1) * 8) * 2);
    // B (non-trans): matrix0/1 = experts 0-7 (k0-7, k8-15); matrix2/3 = experts 8-15
    const uint32_t b_base = (uint32_t)((((q >> 1) * 8) + lr) * 128 + ((q & 1) * 8) * 2);

    // loader indices
    const int xr = tid >> 2, xc = tid & 3;   // x: rows xr, xr+64; 16-float chunk xc
    const int we = tid >> 3, wj = tid & 7;   // W: experts we, we+32; 16B chunk wj

    float acc[8][4];
    #pragma unroll
    for (int i = 0; i < 8; i++)
        #pragma unroll
        for (int j = 0; j < 4; j++) acc[i][j] = 0.0f;

    float4 xv[8];
    uint4 wh[2], wl[2];

    // prefetch stage 0
    {
        const int k0 = 0;
        #pragma unroll
        for (int j = 0; j < 2; j++)
            #pragma unroll
            for (int c = 0; c < 4; c++)
                xv[j * 4 + c] = *(const float4*)&x[(size_t)(m0 + xr + 64 * j) * ND + k0 + xc * 16 + c * 4];
        #pragma unroll
        for (int p = 0; p < 2; p++) {
            const int e = we + 32 * p;
            wh[p] = *(const uint4*)&g_Whi[e * ND + k0 + wj * 8];
            wl[p] = *(const uint4*)&g_Wlo[e * ND + k0 + wj * 8];
        }
    }

    for (int ch = 0; ch < NCH; ch++) {
        __syncthreads();   // previous compute done; safe to overwrite smem

        // store A (split fp32 -> fp16 hi/lo) and B into smem
        #pragma unroll
        for (int j = 0; j < 2; j++) {
            #pragma unroll
            for (int c = 0; c < 4; c++) {
                float4 v = xv[j * 4 + c];
                __half2 h01 = __floats2half2_rn(v.x, v.y);
                __half2 h23 = __floats2half2_rn(v.z, v.w);
                float2 f01 = __half22float2(h01), f23 = __half22float2(h23);
                __half2 l01 = __floats2half2_rn(v.x - f01.x, v.y - f01.y);
                __half2 l23 = __floats2half2_rn(v.z - f23.x, v.w - f23.y);
                uint32_t u0, u1, u2, u3;
                memcpy(&u0, &h01, 4); memcpy(&u1, &h23, 4);
                memcpy(&u2, &l01, 4); memcpy(&u3, &l23, 4);
                const uint32_t so = SW128((uint32_t)((xr + 64 * j) * 128 + (xc * 16 + c * 4) * 2));
                sts64(A_HI + so, u0, u1);
                sts64(A_LO + so, u2, u3);
            }
        }
        #pragma unroll
        for (int p = 0; p < 2; p++) {
            const uint32_t so = SW128((uint32_t)((we + 32 * p) * 128 + wj * 16));
            sts128(B_HI + so, wh[p]);
            sts128(B_LO + so, wl[p]);
        }
        __syncthreads();

        // prefetch next stage into registers (overlaps with MMA below)
        if (ch + 1 < NCH) {
            const int k0 = (ch + 1) * KC;
            #pragma unroll
            for (int j = 0; j < 2; j++)
                #pragma unroll
                for (int c = 0; c < 4; c++)
                    xv[j * 4 + c] = *(const float4*)&x[(size_t)(m0 + xr + 64 * j) * ND + k0 + xc * 16 + c * 4];
            #pragma unroll
            for (int p = 0; p < 2; p++) {
                const int e = we + 32 * p;
                wh[p] = *(const uint4*)&g_Whi[e * ND + k0 + wj * 8];
                wl[p] = *(const uint4*)&g_Wlo[e * ND + k0 + wj * 8];
            }
        }

        // compute: 4 k16 chunks, 8 n8 frags, 3-MMA split
        #pragma unroll
        for (int kc = 0; kc < 4; kc++) {
            uint32_t ah[4], al[4];
            const uint32_t ao = SW128(a_base + kc * 32);
            ldm4(ah, A_HI + ao);
            ldm4(al, A_LO + ao);
            const uint32_t bo = SW128(b_base + kc * 32);
            #pragma unroll
            for (int nb = 0; nb < 4; nb++) {
                uint32_t bh[4], bl[4];
                ldm4(bh, B_HI + bo + nb * 2048);
                ldm4(bl, B_LO + bo + nb * 2048);
                mma16816(acc[2 * nb],     ah, bh[0], bh[1]);
                mma16816(acc[2 * nb],     ah, bl[0], bl[1]);
                mma16816(acc[2 * nb],     al, bh[0], bh[1]);
                mma16816(acc[2 * nb + 1], ah, bh[2], bh[3]);
                mma16816(acc[2 * nb + 1], ah, bl[2], bl[3]);
                mma16816(acc[2 * nb + 1], al, bh[2], bh[3]);
            }
        }
    }

    // ---- dump logits to smem: lg[128][68] ----
    __syncthreads();
    float* lg = (float*)smem;
    const int gid = lane >> 2, tig = lane & 3;
    #pragma unroll
    for (int nf = 0; nf < 8; nf++) {
        const int c0 = nf * 8 + 2 * tig;
        *(float2*)&lg[(wr + gid) * 68 + c0]     = make_float2(acc[nf][0], acc[nf][1]);
        *(float2*)&lg[(wr + gid + 8) * 68 + c0] = make_float2(acc[nf][2], acc[nf][3]);
    }
    __syncthreads();

    // ---- per-token epilogue ----
    if (tid < TM) {
        const int token = m0 + tid;
        float* row = &lg[tid * 68];

        float mx = -3.0e38f;
        #pragma unroll
        for (int j = 0; j < NE / 4; j++) {
            float4 v  = *(float4*)&row[4 * j];
            float4 nz = *(const float4*)&noise[(size_t)token * NE + 4 * j];
            float4 bb = *(const float4*)&bias[4 * j];
            v.x += bb.x + 0.1f * nz.x;
            v.y += bb.y + 0.1f * nz.y;
            v.z += bb.z + 0.1f * nz.z;
            v.w += bb.w + 0.1f * nz.w;
            mx = fmaxf(mx, fmaxf(fmaxf(v.x, v.y), fmaxf(v.z, v.w)));
            *(float4*)&row[4 * j] = v;
        }
        float sum = 0.0f;
        #pragma unroll
        for (int j = 0; j < NE / 4; j++) {
            float4 v = *(float4*)&row[4 * j];
            v.x = expf(v.x - mx);
            v.y = expf(v.y - mx);
            v.z = expf(v.z - mx);
            v.w = expf(v.w - mx);
            sum += (v.x + v.y) + (v.z + v.w);
            *(float4*)&row[4 * j] = v;
        }
        const float inv = 1.0f / sum;

        float m1 = -1.0f, m2 = -1.0f;
        int i1 = 0, i2 = 0;
        float* out_sc = out + (size_t)NM * 4;
        #pragma unroll
        for (int j = 0; j < NE / 4; j++) {
            float4 v = *(float4*)&row[4 * j];
            v.x *= inv; v.y *= inv; v.z *= inv; v.w *= inv;
            *(float4*)&out_sc[(size_t)token * NE + 4 * j] = v;
            float vs[4] = {v.x, v.y, v.z, v.w};
            #pragma unroll
            for (int l = 0; l < 4; l++) {
                const int idx = 4 * j + l;
                const float val = vs[l];
                if (val > m1)      { m2 = m1; i2 = i1; m1 = val; i1 = idx; }
                else if (val > m2) { m2 = val; i2 = idx; }
            }
        }
        out[(size_t)token * 2 + 0] = m1;
        out[(size_t)token * 2 + 1] = m2;
        out[(size_t)NM * 2 + (size_t)token * 2 + 0] = (float)i1;
        out[(size_t)NM * 2 + (size_t)token * 2 + 1] = (float)i2;
    }
}

extern "C" void kernel_launch(void* const* d_in, const int* in_sizes, int n_in,
                              void* d_out, int out_size) {
    const float* x     = (const float*)d_in[0];
    const float* W     = (const float*)d_in[1];
    const float* b     = (const float*)d_in[2];
    const float* noise = (const float*)d_in[3];

    prep_W<<<(NE * ND) / 256, 256>>>(W);
    router_mma<<<NM / TM, 256>>>(x, b, noise, (float*)d_out);
}

// round 7
// speedup vs baseline: 2.4603x; 1.1648x over previous
#include <cuda_runtime.h>
#include <cuda_fp16.h>
#include <cstdint>
#include <cstddef>
#include <cstring>

#define NM 16384
#define ND 2048
#define NE 64
#define TM 256
#define KC 64
#define KHALF 1024
#define NSTG 16            // KHALF / KC

#define XROWB 288          // x row stride bytes (72 floats) -> conflict-free LDS.64
#define XBUF_SZ (TM*XROWB) // 73728 per stage
#define WOFF (2*XBUF_SZ)   // 147456
#define WSTG 16384         // W hi(8K)+lo(8K) per stage
#define SMEM_BYTES (WOFF + 2*WSTG)  // 180224

#define SW128(o) ((o) ^ (((o) >> 3) & 0x70))

__device__ __align__(16) __half g_Whi[NE * ND];
__device__ __align__(16) __half g_Wlo[NE * ND];
__device__ __align__(16) float  g_part[2][NM][NE];   // 8 MB split-K partials

// ---------- helpers ----------
__device__ __forceinline__ uint32_t smem_u32(const void* p) {
    uint32_t a;
    asm("{ .reg .u64 t; cvta.to.shared.u64 t, %1; cvt.u32.u64 %0, t; }" : "=r"(a) : "l"(p));
    return a;
}
__device__ __forceinline__ void cpa16(uint32_t dst, const void* src) {
    uint64_t g = __cvta_generic_to_global((void*)src);
    asm volatile("cp.async.cg.shared.global [%0], [%1], 16;" :: "r"(dst), "l"(g) : "memory");
}
__device__ __forceinline__ void cpa_commit() {
    asm volatile("cp.async.commit_group;" ::: "memory");
}
__device__ __forceinline__ void cpa_wait1() {
    asm volatile("cp.async.wait_group 1;" ::: "memory");
}
__device__ __forceinline__ void ldm4(uint32_t* r, uint32_t addr) {
    asm volatile("ldmatrix.sync.aligned.m8n8.x4.shared.b16 {%0,%1,%2,%3}, [%4];"
                 : "=r"(r[0]), "=r"(r[1]), "=r"(r[2]), "=r"(r[3]) : "r"(addr));
}
__device__ __forceinline__ void mma16816(float* d, const uint32_t* a, uint32_t b0, uint32_t b1) {
    asm volatile(
        "mma.sync.aligned.m16n8k16.row.col.f32.f16.f16.f32 "
        "{%0,%1,%2,%3}, {%4,%5,%6,%7}, {%8,%9}, {%0,%1,%2,%3};"
        : "+f"(d[0]), "+f"(d[1]), "+f"(d[2]), "+f"(d[3])
        : "r"(a[0]), "r"(a[1]), "r"(a[2]), "r"(a[3]), "r"(b0), "r"(b1));
}
__device__ __forceinline__ void split2(float2 v, uint32_t& hi, uint32_t& lo) {
    __half2 h = __floats2half2_rn(v.x, v.y);
    float2 hf = __half22float2(h);
    __half2 l = __floats2half2_rn(v.x - hf.x, v.y - hf.y);
    memcpy(&hi, &h, 4); memcpy(&lo, &l, 4);
}

// ---------- W prep: fp32 [K,E] -> fp16 hi/lo, transposed to [E,K] ----------
__global__ void prep_W(const float* __restrict__ W) {
    int idx = blockIdx.x * 256 + threadIdx.x;
    int e = idx >> 11, k = idx & (ND - 1);
    float w = W[k * NE + e];
    __half h = __float2half_rn(w);
    g_Whi[idx] = h;
    g_Wlo[idx] = __float2half_rn(w - __half2float(h));
}

// ---------- GEMM kernel: 256-token tile x half-K per CTA, partials to gmem ----------
__global__ __launch_bounds__(256, 1)
void router_mma(const float* __restrict__ x)
{
    extern __shared__ __align__(1024) char smem[];
    const uint32_t sb = smem_u32(smem);

    const int tid = threadIdx.x, wid = tid >> 5, lane = tid & 31;
    const int gid = lane >> 2, t = lane & 3;
    const int m0 = blockIdx.x * TM;
    const int z  = blockIdx.y;
    const int kbase = z * KHALF;

    const int q = lane >> 3, lr = lane & 7;
    const uint32_t b_base = (uint32_t)((((q >> 1) * 8) + lr) * 128 + ((q & 1) * 8) * 2);

    float acc[16][4];
    #pragma unroll
    for (int i = 0; i < 16; i++)
        #pragma unroll
        for (int j = 0; j < 4; j++) acc[i][j] = 0.0f;

    // ---- async stage issue ----
    auto issue = [&](int s) {
        if (s < NSTG) {
            const uint32_t xb = sb + (s & 1) * XBUF_SZ;
            const int k0 = kbase + s * KC;
            #pragma unroll
            for (int i = 0; i < 16; i++) {
                const int id = tid + 256 * i;
                const int row = id >> 4, c = id & 15;
                cpa16(xb + row * XROWB + c * 16,
                      &x[(size_t)(m0 + row) * ND + k0 + c * 4]);
            }
            const uint32_t wb = sb + WOFF + (s & 1) * WSTG;
            #pragma unroll
            for (int i = 0; i < 2; i++) {
                const int id = tid + 256 * i;
                const int e = id >> 3, j = id & 7;
                const uint32_t so = SW128((uint32_t)(e * 128 + j * 16));
                cpa16(wb + so,        &g_Whi[e * ND + k0 + j * 8]);
                cpa16(wb + 8192 + so, &g_Wlo[e * ND + k0 + j * 8]);
            }
        }
        cpa_commit();
    };

    issue(0);
    for (int s = 0; s < NSTG; s++) {
        issue(s + 1);
        cpa_wait1();
        __syncthreads();

        const char* xp = smem + (s & 1) * XBUF_SZ;
        const uint32_t wh = sb + WOFF + (s & 1) * WSTG, wlo = wh + 8192;

        #pragma unroll
        for (int kc = 0; kc < 4; kc++) {
            uint32_t bh[4][4], bl[4][4];
            const uint32_t bo = SW128(b_base + kc * 32);
            #pragma unroll
            for (int nb = 0; nb < 4; nb++) {
                ldm4(bh[nb], wh  + bo + nb * 2048);
                ldm4(bl[nb], wlo + bo + nb * 2048);
            }
            #pragma unroll
            for (int sub = 0; sub < 2; sub++) {
                const int row = wid * 32 + sub * 16 + gid;
                const char* rp = xp + row * XROWB + (kc * 16 + 2 * t) * 4;
                float2 a0 = *(const float2*)(rp);
                float2 a1 = *(const float2*)(rp + 8 * XROWB);
                float2 a2 = *(const float2*)(rp + 32);
                float2 a3 = *(const float2*)(rp + 8 * XROWB + 32);
                uint32_t ah[4], al[4];
                split2(a0, ah[0], al[0]);
                split2(a1, ah[1], al[1]);
                split2(a2, ah[2], al[2]);
                split2(a3, ah[3], al[3]);
                #pragma unroll
                for (int nb = 0; nb < 4; nb++) {
                    float* p0 = acc[sub * 8 + 2 * nb];
                    float* p1 = acc[sub * 8 + 2 * nb + 1];
                    mma16816(p0, ah, bh[nb][0], bh[nb][1]);
                    mma16816(p0, ah, bl[nb][0], bl[nb][1]);
                    mma16816(p0, al, bh[nb][0], bh[nb][1]);
                    mma16816(p1, ah, bh[nb][2], bh[nb][3]);
                    mma16816(p1, ah, bl[nb][2], bl[nb][3]);
                    mma16816(p1, al, bh[nb][2], bh[nb][3]);
                }
            }
        }
        __syncthreads();
    }

    // ---- write fp32 partials straight from accumulators ----
    #pragma unroll
    for (int sub = 0; sub < 2; sub++) {
        const int token = m0 + wid * 32 + sub * 16 + gid;
        #pragma unroll
        for (int nf = 0; nf < 8; nf++) {
            const int e0 = nf * 8 + 2 * t;
            float* p = &g_part[z][token][e0];
            *(float2*)p            = make_float2(acc[sub * 8 + nf][0], acc[sub * 8 + nf][1]);
            *(float2*)(p + 8 * NE) = make_float2(acc[sub * 8 + nf][2], acc[sub * 8 + nf][3]);
        }
    }
}

// ---------- combine partials + bias + noise + softmax + top-2 ----------
__global__ __launch_bounds__(256)
void combine(const float* __restrict__ bias, const float* __restrict__ noise,
             float* __restrict__ out)
{
    __shared__ float lg[128 * 68];
    const int tid = threadIdx.x;
    const int t0 = blockIdx.x * 128;
    const float* p0 = &g_part[0][t0][0];
    const float* p1 = &g_part[1][t0][0];

    #pragma unroll
    for (int i = 0; i < 8; i++) {
        const int id = tid + 256 * i;        // float4 index over 128*64 floats
        const int off = id * 4;
        const int row = off >> 6, col = off & 63;
        float4 a = *(const float4*)(p0 + off);
        float4 b = *(const float4*)(p1 + off);
        a.x += b.x; a.y += b.y; a.z += b.z; a.w += b.w;
        *(float4*)&lg[row * 68 + col] = a;
    }
    __syncthreads();

    if (tid < 128) {
        const int token = t0 + tid;
        float* row = &lg[tid * 68];

        float mx = -3.0e38f;
        #pragma unroll
        for (int j = 0; j < NE / 4; j++) {
            float4 v  = *(float4*)&row[4 * j];
            float4 nz = *(const float4*)&noise[(size_t)token * NE + 4 * j];
            float4 bb = *(const float4*)&bias[4 * j];
            v.x += bb.x + 0.1f * nz.x;
            v.y += bb.y + 0.1f * nz.y;
            v.z += bb.z + 0.1f * nz.z;
            v.w += bb.w + 0.1f * nz.w;
            mx = fmaxf(mx, fmaxf(fmaxf(v.x, v.y), fmaxf(v.z, v.w)));
            *(float4*)&row[4 * j] = v;
        }
        float sum = 0.0f;
        #pragma unroll
        for (int j = 0; j < NE / 4; j++) {
            float4 v = *(float4*)&row[4 * j];
            v.x = expf(v.x - mx);
            v.y = expf(v.y - mx);
            v.z = expf(v.z - mx);
            v.w = expf(v.w - mx);
            sum += (v.x + v.y) + (v.z + v.w);
            *(float4*)&row[4 * j] = v;
        }
        const float inv = 1.0f / sum;

        float m1 = -1.0f, m2 = -1.0f;
        int i1 = 0, i2 = 0;
        float* out_sc = out + (size_t)NM * 4;
        #pragma unroll
        for (int j = 0; j < NE / 4; j++) {
            float4 v = *(float4*)&row[4 * j];
            v.x *= inv; v.y *= inv; v.z *= inv; v.w *= inv;
            *(float4*)&out_sc[(size_t)token * NE + 4 * j] = v;
            float vs[4] = {v.x, v.y, v.z, v.w};
            #pragma unroll
            for (int l = 0; l < 4; l++) {
                const int idx = 4 * j + l;
                const float val = vs[l];
                if (val > m1)      { m2 = m1; i2 = i1; m1 = val; i1 = idx; }
                else if (val > m2) { m2 = val; i2 = idx; }
            }
        }
        out[(size_t)token * 2 + 0] = m1;
        out[(size_t)token * 2 + 1] = m2;
        out[(size_t)NM * 2 + (size_t)token * 2 + 0] = (float)i1;
        out[(size_t)NM * 2 + (size_t)token * 2 + 1] = (float)i2;
    }
}

extern "C" void kernel_launch(void* const* d_in, const int* in_sizes, int n_in,
                              void* d_out, int out_size) {
    const float* x     = (const float*)d_in[0];
    const float* W     = (const float*)d_in[1];
    const float* b     = (const float*)d_in[2];
    const float* noise = (const float*)d_in[3];

    cudaFuncSetAttribute(router_mma, cudaFuncAttributeMaxDynamicSharedMemorySize, SMEM_BYTES);

    prep_W<<<(NE * ND) / 256, 256>>>(W);
    router_mma<<<dim3(NM / TM, 2, 1), 256, SMEM_BYTES>>>(x);
    combine<<<NM / 128, 256>>>(b, noise, (float*)d_out);
}